// round 16
// baseline (speedup 1.0000x reference)
#include <cuda_runtime.h>

// YOLOV3TargetMerger — fused single-launch version.
// Shapes fixed by the problem instance: b=32, N=22743, M=50, C=80.
// NOTE: box coords are raw uniform(0,1) — corners UNSORTED, so areas and
// unions can be NEGATIVE. The division-free IOU test must be sign-aware:
//   iou > 0.7  ⇔  (uni > 0) && (inter > 0.7*uni),   uni = ap+ag-inter+eps
// (inter >= 0 always; uni <= 0 ⇒ iou <= 0 ⇒ never a hit.)
//
// Outputs concatenated flat in reference tuple order:
//   objectness    [b,N,1]  at out + 0
//   center_targets[b,N,2]  at out + 1*BN
//   scale_targets [b,N,2]  at out + 3*BN
//   weights       [b,N,2]  at out + 5*BN
//   class_targets [b,N,C]  at out + 7*BN
//   class_mask    [b,N,C]  at out + (7+C)*BN

#define BB   32
#define NN   22743
#define MM   50
#define CC   80
#define BN   ((long long)BB * NN)          // 727776
#define VEC_PER_ANCHOR 20u                 // C/4
#define IGNORE_IOU 0.7f
#define EPS_IOU 1e-12f

#define A_BLOCKS_PER_B ((NN + 255) / 256)          // 89
#define A_BLOCKS       (A_BLOCKS_PER_B * BB)       // 2848
#define B_TOTAL_VEC    14555520u                   // BN * 20, fits in u32
#define B_BLOCKS       ((int)((B_TOTAL_VEC + 255u) / 256u))  // 56858

// ---------------------------------------------------------------------------
// Fused kernel: first A_BLOCKS blocks do per-anchor small fields + IOU test
// (compute-heavy, division-free); remaining blocks do the big class-field
// streaming merge (DRAM-bound). The A-compute hides under B's memory stalls.
// ---------------------------------------------------------------------------
__global__ __launch_bounds__(256)
void yolo_fused_kernel(const float*  __restrict__ box_preds,   // [b,N,4]
                       const float*  __restrict__ gt_boxes,    // [b,M,4]
                       const float*  __restrict__ obj_t,       // [b,N,1]
                       const float*  __restrict__ centers_t,   // [b,N,2]
                       const float*  __restrict__ scales_t,    // [b,N,2]
                       const float*  __restrict__ weights_t,   // [b,N,2]
                       const float4* __restrict__ clas,        // [b,N,C] as float4
                       float* __restrict__ out)
{
    if (blockIdx.x < A_BLOCKS) {
        // ------------------ Part A: small fields + IOU ignore test ---------
        __shared__ float4 s_gt[MM];
        __shared__ float  s_area[MM];

        const int b   = blockIdx.x / A_BLOCKS_PER_B;
        const int nbk = blockIdx.x % A_BLOCKS_PER_B;
        const int tid = threadIdx.x;

        if (tid < MM) {
            float4 g = reinterpret_cast<const float4*>(gt_boxes)[(long long)b * MM + tid];
            s_gt[tid]   = g;
            s_area[tid] = (g.z - g.x) * (g.w - g.y);
        }
        __syncthreads();

        const int n = nbk * 256 + tid;
        if (n >= NN) return;
        const long long a = (long long)b * NN + n;

        const float obj  = obj_t[a];
        const bool  mask = obj > 0.0f;

        float objout;
        if (mask) {
            objout = obj;          // dynamic target is dead code -> skip IOU
        } else {
            const float4 p  = reinterpret_cast<const float4*>(box_preds)[a];
            const float  ap = (p.z - p.x) * (p.w - p.y);
            bool hit = false;
            // Sign-aware division-free test (areas/unions may be negative!):
            // iou > 0.7  <=>  uni > 0  &&  inter > 0.7*uni
            #pragma unroll
            for (int m = 0; m < MM; ++m) {
                const float4 g = s_gt[m];
                const float tlx = fmaxf(p.x, g.x);
                const float tly = fmaxf(p.y, g.y);
                const float brx = fminf(p.z, g.z);
                const float bry = fminf(p.w, g.w);
                const float w = fmaxf(brx - tlx, 0.0f);
                const float h = fmaxf(bry - tly, 0.0f);
                const float inter = w * h;
                const float uni   = ap + s_area[m] - inter + EPS_IOU;
                hit = hit | ((uni > 0.0f) & (inter > IGNORE_IOU * uni));
            }
            objout = hit ? -1.0f : 0.0f;
        }

        __stcs(out + a, objout);

        float2 c, s, w;
        if (mask) {
            c = reinterpret_cast<const float2*>(centers_t)[a];
            s = reinterpret_cast<const float2*>(scales_t)[a];
            w = reinterpret_cast<const float2*>(weights_t)[a];
        } else {
            c = make_float2(0.0f, 0.0f);
            s = make_float2(0.0f, 0.0f);
            w = make_float2(0.0f, 0.0f);
        }
        __stcs(reinterpret_cast<float2*>(out + 1 * BN) + a, c);
        __stcs(reinterpret_cast<float2*>(out + 3 * BN) + a, s);
        __stcs(reinterpret_cast<float2*>(out + 5 * BN) + a, w);
    } else {
        // ------------------ Part B: class_targets + class_mask -------------
        const unsigned int i = (blockIdx.x - A_BLOCKS) * 256u + threadIdx.x;
        if (i >= B_TOTAL_VEC) return;

        const unsigned int anchor = i / VEC_PER_ANCHOR;  // u32 const-div -> IMAD.HI
        const bool mask = __ldg(obj_t + anchor) > 0.0f;

        float4* __restrict__ class_t = reinterpret_cast<float4*>(out + 7 * BN);
        float4* __restrict__ class_m = reinterpret_cast<float4*>(out + (7 + CC) * BN);

        float4 t, m;
        if (mask) {
            const float4 v = __ldcs(clas + i);           // single-use: stream it
            t = v;
            m = make_float4(v.x >= 0.0f ? 1.0f : 0.0f,
                            v.y >= 0.0f ? 1.0f : 0.0f,
                            v.z >= 0.0f ? 1.0f : 0.0f,
                            v.w >= 0.0f ? 1.0f : 0.0f);
        } else {
            t = make_float4(-1.0f, -1.0f, -1.0f, -1.0f);
            m = make_float4(0.0f, 0.0f, 0.0f, 0.0f);
        }
        __stcs(class_t + i, t);
        __stcs(class_m + i, m);
    }
}

// ---------------------------------------------------------------------------
extern "C" void kernel_launch(void* const* d_in, const int* in_sizes, int n_in,
                              void* d_out, int out_size)
{
    const float* box_preds = (const float*)d_in[0];
    const float* gt_boxes  = (const float*)d_in[1];
    const float* obj_t     = (const float*)d_in[2];
    const float* centers_t = (const float*)d_in[3];
    const float* scales_t  = (const float*)d_in[4];
    const float* weights_t = (const float*)d_in[5];
    const float* clas_t    = (const float*)d_in[6];
    float* out = (float*)d_out;

    const int grid = A_BLOCKS + B_BLOCKS;   // 2848 + 56858 = 59706
    yolo_fused_kernel<<<grid, 256>>>(box_preds, gt_boxes, obj_t,
                                     centers_t, scales_t, weights_t,
                                     (const float4*)clas_t, out);
}